// round 15
// baseline (speedup 1.0000x reference)
#include <cuda_runtime.h>
#include <cuda_fp16.h>
#include <math.h>
#include <stdint.h>

#define BATCH 2
#define L 192
#define D 384
#define H 8
#define DH 48
#define EPS 1e-5f
#define SCALE 0.14433756729740643f   // 1/sqrt(48)

// ---------------- scratch (device globals) ----------------------------------
__device__ __align__(16) float g_xn[BATCH * L * D];
__device__ __align__(16) __half g_xn_hi[BATCH * L * D];
__device__ __align__(16) __half g_xn_lo[BATCH * L * D];
__device__ __align__(16) float g_v[BATCH * L * D];
__device__ __align__(16) float g_dots[BATCH * H * L * L];
__device__ __align__(16) float g_ctx[BATCH * L * D];
// fp16 u weights in NATIVE [r][k][n] layout (no transpose)
__device__ __align__(16) __half g_uq16[L * D * D];
__device__ __align__(16) __half g_uk16[L * D * D];

// ---------------- helpers -----------------------------------------------------
__device__ __forceinline__ uint32_t smem_u32(const void* p) {
    uint32_t a;
    asm("{ .reg .u64 t; cvta.to.shared.u64 t, %1; cvt.u32.u64 %0, t; }"
        : "=r"(a) : "l"(p));
    return a;
}
__device__ __forceinline__ void ldmx4(uint32_t* f, uint32_t a) {
    asm volatile("ldmatrix.sync.aligned.m8n8.x4.shared.b16 {%0,%1,%2,%3}, [%4];"
                 : "=r"(f[0]), "=r"(f[1]), "=r"(f[2]), "=r"(f[3]) : "r"(a));
}
__device__ __forceinline__ void ldmx4t(uint32_t* f, uint32_t a) {
    asm volatile("ldmatrix.sync.aligned.m8n8.x4.trans.shared.b16 {%0,%1,%2,%3}, [%4];"
                 : "=r"(f[0]), "=r"(f[1]), "=r"(f[2]), "=r"(f[3]) : "r"(a));
}
__device__ __forceinline__ void mma16816h(float* c, const uint32_t* a, const uint32_t* b) {
    asm volatile(
        "mma.sync.aligned.m16n8k16.row.col.f32.f16.f16.f32 "
        "{%0,%1,%2,%3}, {%4,%5,%6,%7}, {%8,%9}, {%0,%1,%2,%3};"
        : "+f"(c[0]), "+f"(c[1]), "+f"(c[2]), "+f"(c[3])
        : "r"(a[0]), "r"(a[1]), "r"(a[2]), "r"(a[3]), "r"(b[0]), "r"(b[1]));
}
#define CP16(dst, src) \
    asm volatile("cp.async.cg.shared.global [%0], [%1], 16;" :: "r"(dst), "l"(src))
#define CP16Z(dst) \
    asm volatile("cp.async.cg.shared.global [%0], [%1], 16, 0;" \
                 :: "r"(dst), "l"((const void*)g_xn_hi))
#define CP_COMMIT() asm volatile("cp.async.commit_group;" ::: "memory")
#define CP_WAIT1()  asm volatile("cp.async.wait_group 1;" ::: "memory")

// ---------------- streaming fp32 -> fp16 convert of u (no transpose) ---------
__global__ __launch_bounds__(256) void conv_kernel(const float* __restrict__ uq,
                                                   const float* __restrict__ uk) {
    size_t idx = ((size_t)blockIdx.x * 256 + threadIdx.x) * 4;
    float4 a = *(const float4*)(uq + idx);
    float4 b = *(const float4*)(uk + idx);
    __half2 a0 = __floats2half2_rn(a.x, a.y), a1 = __floats2half2_rn(a.z, a.w);
    __half2 b0 = __floats2half2_rn(b.x, b.y), b1 = __floats2half2_rn(b.z, b.w);
    *(uint2*)(g_uq16 + idx) = make_uint2(*(uint32_t*)&a0, *(uint32_t*)&a1);
    *(uint2*)(g_uk16 + idx) = make_uint2(*(uint32_t*)&b0, *(uint32_t*)&b1);
}

// ---------------- LayerNorm (+ fp16 hi/lo emit) -------------------------------
__global__ void ln_kernel(const float* __restrict__ x,
                          const float* __restrict__ gamma,
                          const float* __restrict__ beta) {
    int row = blockIdx.x;
    const float* xr = x + (size_t)row * D;
    float* o = g_xn + (size_t)row * D;
    __half* ohi = g_xn_hi + (size_t)row * D;
    __half* olo = g_xn_lo + (size_t)row * D;
    int t = threadIdx.x;
    float v0 = xr[t], v1 = xr[t + 128], v2 = xr[t + 256];
    float s = v0 + v1 + v2;
    float sq = v0 * v0 + v1 * v1 + v2 * v2;
    #pragma unroll
    for (int off = 16; off; off >>= 1) {
        s  += __shfl_xor_sync(0xffffffffu, s,  off);
        sq += __shfl_xor_sync(0xffffffffu, sq, off);
    }
    __shared__ float ss[4], ssq[4];
    int w = t >> 5;
    if ((t & 31) == 0) { ss[w] = s; ssq[w] = sq; }
    __syncthreads();
    __shared__ float smu, srstd;
    if (t == 0) {
        float a = ss[0] + ss[1] + ss[2] + ss[3];
        float b2 = ssq[0] + ssq[1] + ssq[2] + ssq[3];
        float mu = a * (1.0f / D);
        float var = b2 * (1.0f / D) - mu * mu;
        smu = mu;
        srstd = rsqrtf(var + EPS);
    }
    __syncthreads();
    float mu = smu, rstd = srstd;
    #pragma unroll
    for (int seg = 0; seg < 3; ++seg) {
        int c = t + seg * 128;
        float v = (seg == 0 ? v0 : (seg == 1 ? v1 : v2));
        float on = (v - mu) * rstd * gamma[c] + beta[c];
        o[c] = on;
        __half h = __float2half_rn(on);
        ohi[c] = h;
        olo[c] = __float2half_rn(on - __half2float(h));
    }
}

// ---------------- generic 384^3 GEMM body ------------------------------------
template <bool HAS_BIAS>
__device__ __forceinline__ void gemm384_body(
    const float* __restrict__ A, const float* __restrict__ Bm,
    const float* __restrict__ bias, float* __restrict__ C) {
    __shared__ float sA[16][64];
    __shared__ float sB[16][64];
    int bm = blockIdx.y * 64, bn = blockIdx.x * 64;
    int t = threadIdx.x;
    int tx = t & 15, ty = t >> 4;
    float acc[4][4] = {};
    for (int k0 = 0; k0 < 384; k0 += 16) {
        {
            int m = t >> 2, f = t & 3;
            float4 av = *(const float4*)(A + (size_t)(bm + m) * 384 + k0 + f * 4);
            sA[f * 4 + 0][m] = av.x; sA[f * 4 + 1][m] = av.y;
            sA[f * 4 + 2][m] = av.z; sA[f * 4 + 3][m] = av.w;
        }
        {
            int kk = t >> 4, n4 = t & 15;
            *(float4*)&sB[kk][n4 * 4] =
                *(const float4*)(Bm + (size_t)(k0 + kk) * 384 + bn + n4 * 4);
        }
        __syncthreads();
        #pragma unroll
        for (int kk = 0; kk < 16; ++kk) {
            float4 a4 = *(const float4*)&sA[kk][ty * 4];
            float4 b4 = *(const float4*)&sB[kk][tx * 4];
            float av[4] = {a4.x, a4.y, a4.z, a4.w};
            float bv[4] = {b4.x, b4.y, b4.z, b4.w};
            #pragma unroll
            for (int i = 0; i < 4; ++i)
                #pragma unroll
                for (int j = 0; j < 4; ++j)
                    acc[i][j] += av[i] * bv[j];
        }
        __syncthreads();
    }
    #pragma unroll
    for (int i = 0; i < 4; ++i)
        #pragma unroll
        for (int j = 0; j < 4; ++j) {
            float v = acc[i][j];
            if (HAS_BIAS) v += bias[bn + tx * 4 + j];
            C[(size_t)(bm + ty * 4 + i) * 384 + bn + tx * 4 + j] = v;
        }
}
__global__ __launch_bounds__(256) void vproj_kernel(const float* __restrict__ wv) {
    gemm384_body<false>(g_xn, wv, nullptr, g_v);
}
__global__ __launch_bounds__(256) void oproj_kernel(const float* __restrict__ wo,
                                                    const float* __restrict__ bo,
                                                    float* __restrict__ out) {
    gemm384_body<true>(g_ctx, wo, bo, out);
}

// ---------------- diagonal dual-GEMM (fp16 2-term, k32 chunks) ---------------
// grid (6 mtiles, 192 r), 256 threads = 8 warps (2m x 2n x 2qk).
// Block: 64 stacked rows x 96 cols (quarter), K=384 in 12 k32 chunks.
// Each stage = two k16 sub-tiles (identical layout to R13). 3 stages, 87KB.
#define B_OFF    8192
#define SUBSTG   14848          // one k16 sub-stage: 8192 A + 2*3328 B
#define STG      (2 * SUBSTG)   // 29696
#define SMEM_TOT (3 * STG)      // 89088
#define SWO(row, koff) ((row) * 32 + ((koff) ^ (((row) & 4) << 2)))

__global__ __launch_bounds__(256, 2) void diag_mma_kernel() {
    int r = blockIdx.y;
    int mtile = blockIdx.x;
    int M = L - r;
    int rows2 = 2 * M;
    int m0 = mtile * 64;
    if (m0 >= rows2) return;

    extern __shared__ __align__(16) uint8_t smd[];
    uint32_t su = smem_u32(smd);
    int tid = threadIdx.x, lane = tid & 31, wid = tid >> 5;
    int wm = wid & 1, wn = (wid >> 1) & 1, qk = wid >> 2;

    // ---- precomputed cp.async slots (per k16 sub-tile): 2 A + up to 2 B -----
    const __half* aptr[2];
    uint32_t adst[2];
    bool azero[2];
    #pragma unroll
    for (int i = 0; i < 2; ++i) {
        int idx = tid + i * 256;
        int tile = idx >> 7, rem = idx & 127, m = rem >> 1, v = rem & 1;
        adst[i] = tile * 2048 + SWO(m, v * 16);
        int isQ = tile < 2, isLo = tile & 1;
        int g = m0 + m;
        azero[i] = g >= rows2;
        int bb = g >= M;
        int mm = g - (bb ? M : 0);
        if (azero[i]) { bb = 0; mm = 0; }
        int xrow = bb * L + (isQ ? r + mm : mm);
        aptr[i] = (isLo ? g_xn_lo : g_xn_hi) + (size_t)xrow * D + v * 8;
    }
    const __half* bptr[2];
    uint32_t bdst[2];
    bool bval1 = tid < 128;
    #pragma unroll
    for (int i = 0; i < 2; ++i) {
        int j = tid + i * 256;
        if (j >= 384) j = 0;
        int mat = j / 192, rem = j % 192, kl = rem / 12, gran = rem % 12;
        bdst[i] = B_OFF + mat * 3328 + kl * 208 + gran * 16;
        int ridx = mat ? r : (L - 1 - r);
        bptr[i] = (mat ? g_uk16 : g_uq16) + ((size_t)ridx * D + kl) * D + gran * 8;
    }

    auto issue = [&](int ch, int st, int qcol) {
        uint32_t sb = su + st * STG;
        #pragma unroll
        for (int sub = 0; sub < 2; ++sub) {
            uint32_t sbs = sb + sub * SUBSTG;
            int ka = ch * 32 + sub * 16;
            size_t kb = (size_t)ka * D + qcol;
            #pragma unroll
            for (int i = 0; i < 2; ++i) {
                uint32_t dst = sbs + adst[i];
                if (azero[i]) CP16Z(dst);
                else          CP16(dst, aptr[i] + ka);
            }
            CP16(sbs + bdst[0], bptr[0] + kb);
            if (bval1) CP16(sbs + bdst[1], bptr[1] + kb);
        }
    };

    uint32_t aoff = qk * 4096;
    int arow = (lane & 8) + (lane & 7);
    uint32_t au = (uint32_t)(lane >> 4) * 16;
    uint32_t brow_off = (uint32_t)(lane & 15) * 208 + ((uint32_t)(lane >> 4) << 4);

    for (int quarter = 0; quarter < 4; ++quarter) {
        int qcol = quarter * 96;
        float acc[2][6][4] = {};

        issue(0, 0, qcol); CP_COMMIT();
        issue(1, 1, qcol); CP_COMMIT();

        for (int ch = 0; ch < 12; ++ch) {
            int st = ch - (ch / 3) * 3;
            CP_WAIT1();
            __syncthreads();
            if (ch + 2 < 12) issue(ch + 2, (ch + 2) % 3, qcol);
            CP_COMMIT();
            #pragma unroll
            for (int sub = 0; sub < 2; ++sub) {
                uint32_t sbs = su + st * STG + sub * SUBSTG;
                uint32_t sa = sbs + aoff;
                uint32_t af[2][2][4];
                #pragma unroll
                for (int band = 0; band < 2; ++band) {
                    int rb = wm * 32 + band * 16 + arow;
                    uint32_t ab = sa + SWO(rb, au);
                    ldmx4(af[band][0], ab);           // hi
                    ldmx4(af[band][1], ab + 2048);    // lo
                }
                uint32_t sbB = sbs + B_OFF + qk * 3328 + brow_off;
                #pragma unroll
                for (int np = 0; np < 3; ++np) {
                    int cb = wn * 48 + np * 16;
                    uint32_t bh[4];
                    ldmx4t(bh, sbB + cb * 2);
                    #pragma unroll
                    for (int band = 0; band < 2; ++band)
                        #pragma unroll
                        for (int sub2 = 0; sub2 < 2; ++sub2) {
                            float* a4 = acc[band][2 * np + sub2];
                            mma16816h(a4, af[band][0], bh + 2 * sub2);
                            mma16816h(a4, af[band][1], bh + 2 * sub2);
                        }
                }
            }
        }

        // ---- epilogue: exchange K accs via smem, rowwise dot ---------------
        __syncthreads();
        float (*sEx)[97] = (float (*)[97])smd;
        if (qk == 1) {
            #pragma unroll
            for (int band = 0; band < 2; ++band)
                #pragma unroll
                for (int h = 0; h < 2; ++h) {
                    int row = wm * 32 + band * 16 + (lane >> 2) + 8 * h;
                    #pragma unroll
                    for (int nt = 0; nt < 6; ++nt) {
                        int c0 = wn * 48 + nt * 8 + (lane & 3) * 2;
                        sEx[row][c0] = acc[band][nt][2 * h];
                        sEx[row][c0 + 1] = acc[band][nt][2 * h + 1];
                    }
                }
        }
        __syncthreads();
        if (qk == 0) {
            #pragma unroll
            for (int band = 0; band < 2; ++band)
                #pragma unroll
                for (int h = 0; h < 2; ++h) {
                    int row = wm * 32 + band * 16 + (lane >> 2) + 8 * h;
                    float p = 0.f;
                    #pragma unroll
                    for (int nt = 0; nt < 6; ++nt) {
                        int c0 = wn * 48 + nt * 8 + (lane & 3) * 2;
                        p += acc[band][nt][2 * h] * sEx[row][c0]
                           + acc[band][nt][2 * h + 1] * sEx[row][c0 + 1];
                    }
                    p += __shfl_xor_sync(0xffffffffu, p, 1);
                    p += __shfl_xor_sync(0xffffffffu, p, 2);
                    if ((lane & 3) == 0) {
                        int g = m0 + row;
                        if (g < rows2) {
                            int bb = g >= M;
                            int mm = g - (bb ? M : 0);
                            int i = r + mm, j = mm;
                            int head = quarter * 2 + wn;
                            g_dots[((size_t)(bb * H + head) * L + i) * L + j] = p * SCALE;
                        }
                    }
                }
        }
        __syncthreads();
    }
}

// ---------------- softmax + attn @ v -----------------------------------------
__global__ __launch_bounds__(192) void softmax_av_kernel() {
    int i = blockIdx.x, h = blockIdx.y, b = blockIdx.z;
    int t = threadIdx.x;
    const float* drow = g_dots + ((size_t)(b * H + h) * L + i) * L;

    __shared__ float sP[192];
    __shared__ float swork[6];
    __shared__ float smax, ssum;
    __shared__ float sAcc[4][48];

    float val = (t <= i) ? drow[t] : -INFINITY;
    float m = val;
    #pragma unroll
    for (int off = 16; off; off >>= 1)
        m = fmaxf(m, __shfl_xor_sync(0xffffffffu, m, off));
    if ((t & 31) == 0) swork[t >> 5] = m;
    __syncthreads();
    if (t == 0) {
        float mm = swork[0];
        #pragma unroll
        for (int k = 1; k < 6; ++k) mm = fmaxf(mm, swork[k]);
        smax = mm;
    }
    __syncthreads();
    float p = (t <= i) ? expf(val - smax) : 0.f;
    sP[t] = p;
    float s = p;
    #pragma unroll
    for (int off = 16; off; off >>= 1)
        s += __shfl_xor_sync(0xffffffffu, s, off);
    if ((t & 31) == 0) swork[t >> 5] = s;
    __syncthreads();
    if (t == 0) {
        float acc = 0.f;
        #pragma unroll
        for (int k = 0; k < 6; ++k) acc += swork[k];
        ssum = acc;
    }
    __syncthreads();
    float inv = 1.0f / ssum;

    int d = t % 48, q = t / 48;
    float acc = 0.f;
    for (int j = q; j <= i; j += 4)
        acc += sP[j] * g_v[(size_t)(b * L + j) * D + h * DH + d];
    sAcc[q][d] = acc;
    __syncthreads();
    if (t < 48) {
        float o = (sAcc[0][t] + sAcc[1][t] + sAcc[2][t] + sAcc[3][t]) * inv;
        g_ctx[(size_t)(b * L + i) * D + h * DH + t] = o;
    }
}

extern "C" void kernel_launch(void* const* d_in, const int* in_sizes, int n_in,
                              void* d_out, int out_size) {
    const float* x     = (const float*)d_in[0];
    const float* gamma = (const float*)d_in[1];
    const float* beta  = (const float*)d_in[2];
    const float* uq    = (const float*)d_in[3];
    const float* uk    = (const float*)d_in[4];
    const float* wv    = (const float*)d_in[5];
    const float* wo    = (const float*)d_in[6];
    const float* bo    = (const float*)d_in[7];
    float* out = (float*)d_out;
    (void)in_sizes; (void)n_in; (void)out_size;

    cudaFuncSetAttribute(diag_mma_kernel,
                         cudaFuncAttributeMaxDynamicSharedMemorySize, SMEM_TOT);

    // 1) streaming fp32->fp16 convert of u (native layout, no transpose)
    conv_kernel<<<(L * D * D) / 1024, 256>>>(uq, uk);
    // 2) LayerNorm (+ fp16 hi/lo)
    ln_kernel<<<BATCH * L, 128>>>(x, gamma, beta);
    // 3) v = xn @ w_v
    vproj_kernel<<<dim3(6, 6), 256>>>(wv);
    // 4) per-diagonal dual GEMM + per-head dots (fp16 2-term, k32 chunks)
    diag_mma_kernel<<<dim3(6, L), 256, SMEM_TOT>>>();
    // 5) causal softmax + attn @ v
    softmax_av_kernel<<<dim3(L, H, BATCH), 192>>>();
    // 6) out = ctx @ w_o + b_o
    oproj_kernel<<<dim3(6, 6), 256>>>(wo, bo, out);
}

// round 16
// speedup vs baseline: 1.2632x; 1.2632x over previous
#include <cuda_runtime.h>
#include <cuda_fp16.h>
#include <math.h>
#include <stdint.h>

#define BATCH 2
#define L 192
#define D 384
#define H 8
#define DH 48
#define EPS 1e-5f
#define SCALE 0.14433756729740643f   // 1/sqrt(48)

// ---------------- scratch (device globals) ----------------------------------
__device__ __align__(16) float g_xn[BATCH * L * D];
__device__ __align__(16) __half g_xn16[BATCH * L * D];
__device__ __align__(16) float g_v[BATCH * L * D];
__device__ __align__(16) float g_dots[BATCH * H * L * L];
__device__ __align__(16) float g_ctx[BATCH * L * D];
// fp16 u weights in NATIVE [r][k][n] layout (no transpose)
__device__ __align__(16) __half g_uq16[L * D * D];
__device__ __align__(16) __half g_uk16[L * D * D];

// ---------------- helpers -----------------------------------------------------
__device__ __forceinline__ uint32_t smem_u32(const void* p) {
    uint32_t a;
    asm("{ .reg .u64 t; cvta.to.shared.u64 t, %1; cvt.u32.u64 %0, t; }"
        : "=r"(a) : "l"(p));
    return a;
}
__device__ __forceinline__ void ldmx4(uint32_t* f, uint32_t a) {
    asm volatile("ldmatrix.sync.aligned.m8n8.x4.shared.b16 {%0,%1,%2,%3}, [%4];"
                 : "=r"(f[0]), "=r"(f[1]), "=r"(f[2]), "=r"(f[3]) : "r"(a));
}
__device__ __forceinline__ void ldmx4t(uint32_t* f, uint32_t a) {
    asm volatile("ldmatrix.sync.aligned.m8n8.x4.trans.shared.b16 {%0,%1,%2,%3}, [%4];"
                 : "=r"(f[0]), "=r"(f[1]), "=r"(f[2]), "=r"(f[3]) : "r"(a));
}
__device__ __forceinline__ void mma16816h(float* c, const uint32_t* a, const uint32_t* b) {
    asm volatile(
        "mma.sync.aligned.m16n8k16.row.col.f32.f16.f16.f32 "
        "{%0,%1,%2,%3}, {%4,%5,%6,%7}, {%8,%9}, {%0,%1,%2,%3};"
        : "+f"(c[0]), "+f"(c[1]), "+f"(c[2]), "+f"(c[3])
        : "r"(a[0]), "r"(a[1]), "r"(a[2]), "r"(a[3]), "r"(b[0]), "r"(b[1]));
}
#define CP16(dst, src) \
    asm volatile("cp.async.cg.shared.global [%0], [%1], 16;" :: "r"(dst), "l"(src))
#define CP16Z(dst) \
    asm volatile("cp.async.cg.shared.global [%0], [%1], 16, 0;" \
                 :: "r"(dst), "l"((const void*)g_xn16))
#define CP_COMMIT() asm volatile("cp.async.commit_group;" ::: "memory")
#define CP_WAIT2()  asm volatile("cp.async.wait_group 2;" ::: "memory")

// ---------------- streaming fp32 -> fp16 convert of u (no transpose) ---------
__global__ __launch_bounds__(256) void conv_kernel(const float* __restrict__ uq,
                                                   const float* __restrict__ uk) {
    size_t idx = ((size_t)blockIdx.x * 256 + threadIdx.x) * 4;
    float4 a = *(const float4*)(uq + idx);
    float4 b = *(const float4*)(uk + idx);
    __half2 a0 = __floats2half2_rn(a.x, a.y), a1 = __floats2half2_rn(a.z, a.w);
    __half2 b0 = __floats2half2_rn(b.x, b.y), b1 = __floats2half2_rn(b.z, b.w);
    *(uint2*)(g_uq16 + idx) = make_uint2(*(uint32_t*)&a0, *(uint32_t*)&a1);
    *(uint2*)(g_uk16 + idx) = make_uint2(*(uint32_t*)&b0, *(uint32_t*)&b1);
}

// ---------------- LayerNorm (+ fp16 emit) -------------------------------------
__global__ void ln_kernel(const float* __restrict__ x,
                          const float* __restrict__ gamma,
                          const float* __restrict__ beta) {
    int row = blockIdx.x;
    const float* xr = x + (size_t)row * D;
    float* o = g_xn + (size_t)row * D;
    __half* oh = g_xn16 + (size_t)row * D;
    int t = threadIdx.x;
    float v0 = xr[t], v1 = xr[t + 128], v2 = xr[t + 256];
    float s = v0 + v1 + v2;
    float sq = v0 * v0 + v1 * v1 + v2 * v2;
    #pragma unroll
    for (int off = 16; off; off >>= 1) {
        s  += __shfl_xor_sync(0xffffffffu, s,  off);
        sq += __shfl_xor_sync(0xffffffffu, sq, off);
    }
    __shared__ float ss[4], ssq[4];
    int w = t >> 5;
    if ((t & 31) == 0) { ss[w] = s; ssq[w] = sq; }
    __syncthreads();
    __shared__ float smu, srstd;
    if (t == 0) {
        float a = ss[0] + ss[1] + ss[2] + ss[3];
        float b2 = ssq[0] + ssq[1] + ssq[2] + ssq[3];
        float mu = a * (1.0f / D);
        float var = b2 * (1.0f / D) - mu * mu;
        smu = mu;
        srstd = rsqrtf(var + EPS);
    }
    __syncthreads();
    float mu = smu, rstd = srstd;
    #pragma unroll
    for (int seg = 0; seg < 3; ++seg) {
        int c = t + seg * 128;
        float v = (seg == 0 ? v0 : (seg == 1 ? v1 : v2));
        float on = (v - mu) * rstd * gamma[c] + beta[c];
        o[c] = on;
        oh[c] = __float2half_rn(on);
    }
}

// ---------------- generic 384^3 GEMM body ------------------------------------
template <bool HAS_BIAS>
__device__ __forceinline__ void gemm384_body(
    const float* __restrict__ A, const float* __restrict__ Bm,
    const float* __restrict__ bias, float* __restrict__ C) {
    __shared__ float sA[16][64];
    __shared__ float sB[16][64];
    int bm = blockIdx.y * 64, bn = blockIdx.x * 64;
    int t = threadIdx.x;
    int tx = t & 15, ty = t >> 4;
    float acc[4][4] = {};
    for (int k0 = 0; k0 < 384; k0 += 16) {
        {
            int m = t >> 2, f = t & 3;
            float4 av = *(const float4*)(A + (size_t)(bm + m) * 384 + k0 + f * 4);
            sA[f * 4 + 0][m] = av.x; sA[f * 4 + 1][m] = av.y;
            sA[f * 4 + 2][m] = av.z; sA[f * 4 + 3][m] = av.w;
        }
        {
            int kk = t >> 4, n4 = t & 15;
            *(float4*)&sB[kk][n4 * 4] =
                *(const float4*)(Bm + (size_t)(k0 + kk) * 384 + bn + n4 * 4);
        }
        __syncthreads();
        #pragma unroll
        for (int kk = 0; kk < 16; ++kk) {
            float4 a4 = *(const float4*)&sA[kk][ty * 4];
            float4 b4 = *(const float4*)&sB[kk][tx * 4];
            float av[4] = {a4.x, a4.y, a4.z, a4.w};
            float bv[4] = {b4.x, b4.y, b4.z, b4.w};
            #pragma unroll
            for (int i = 0; i < 4; ++i)
                #pragma unroll
                for (int j = 0; j < 4; ++j)
                    acc[i][j] += av[i] * bv[j];
        }
        __syncthreads();
    }
    #pragma unroll
    for (int i = 0; i < 4; ++i)
        #pragma unroll
        for (int j = 0; j < 4; ++j) {
            float v = acc[i][j];
            if (HAS_BIAS) v += bias[bn + tx * 4 + j];
            C[(size_t)(bm + ty * 4 + i) * 384 + bn + tx * 4 + j] = v;
        }
}
__global__ __launch_bounds__(256) void vproj_kernel(const float* __restrict__ wv) {
    gemm384_body<false>(g_xn, wv, nullptr, g_v);
}
__global__ __launch_bounds__(256) void oproj_kernel(const float* __restrict__ wo,
                                                    const float* __restrict__ bo,
                                                    float* __restrict__ out) {
    gemm384_body<true>(g_ctx, wo, bo, out);
}

// ---------------- diagonal dual-GEMM (single-term fp16 mma) ------------------
// grid (6 mtiles, 192 r), 256 threads = 8 warps (2m x 2n x 2qk).
// Block: 64 stacked rows x 96 cols (quarter), K=384 in 24 k16 chunks.
// A: fp16 xn tiles (Q,K), 32B swizzled pitch, 4KB/stage.
// B: fp16 [k16][n96] native-layout tiles, 208B pitch, ldmatrix.x4.trans.
// 4-stage cp.async; 10.75KB/stage (43KB total).
#define B_OFF    4096
#define STG      10752          // 4096 A + 2*3328 B
#define SMEM_TOT (4 * STG)      // 43008
#define SWO(row, koff) ((row) * 32 + ((koff) ^ (((row) & 4) << 2)))

__global__ __launch_bounds__(256, 2) void diag_mma_kernel() {
    int r = blockIdx.y;
    int mtile = blockIdx.x;
    int M = L - r;
    int rows2 = 2 * M;
    int m0 = mtile * 64;
    if (m0 >= rows2) return;

    extern __shared__ __align__(16) uint8_t smd[];
    uint32_t su = smem_u32(smd);
    int tid = threadIdx.x, lane = tid & 31, wid = tid >> 5;
    int wm = wid & 1, wn = (wid >> 1) & 1, qk = wid >> 2;

    // ---- precomputed cp.async slots: 1 A + up to 2 B per thread -------------
    // A: 256 slots = 2 tiles (Q,K) x 64 rows x 2 granules
    const __half* aptr;
    uint32_t adst;
    bool azero;
    {
        int tile = tid >> 7, rem = tid & 127, m = rem >> 1, v = rem & 1;
        adst = tile * 2048 + SWO(m, v * 16);
        int g = m0 + m;
        azero = g >= rows2;
        int bb = g >= M;
        int mm = g - (bb ? M : 0);
        if (azero) { bb = 0; mm = 0; }
        int xrow = bb * L + (tile == 0 ? r + mm : mm);
        aptr = g_xn16 + (size_t)xrow * D + v * 8;
    }
    // B: 384 slots = 2 mats x 16 k-rows x 12 16B-granules
    const __half* bptr[2];
    uint32_t bdst[2];
    bool bval1 = tid < 128;
    #pragma unroll
    for (int i = 0; i < 2; ++i) {
        int j = tid + i * 256;
        if (j >= 384) j = 0;
        int mat = j / 192, rem = j % 192, kl = rem / 12, gran = rem % 12;
        bdst[i] = B_OFF + mat * 3328 + kl * 208 + gran * 16;
        int ridx = mat ? r : (L - 1 - r);
        bptr[i] = (mat ? g_uk16 : g_uq16) + ((size_t)ridx * D + kl) * D + gran * 8;
    }

    auto issue = [&](int ch, int st, int qcol) {
        uint32_t sb = su + st * STG;
        int ka = ch * 16;
        size_t kb = (size_t)ka * D + qcol;
        {
            uint32_t dst = sb + adst;
            if (azero) CP16Z(dst);
            else       CP16(dst, aptr + ka);
        }
        CP16(sb + bdst[0], bptr[0] + kb);
        if (bval1) CP16(sb + bdst[1], bptr[1] + kb);
    };

    uint32_t aoff = qk * 2048;
    int arow = (lane & 8) + (lane & 7);
    uint32_t au = (uint32_t)(lane >> 4) * 16;
    uint32_t brow_off = (uint32_t)(lane & 15) * 208 + ((uint32_t)(lane >> 4) << 4);

    for (int quarter = 0; quarter < 4; ++quarter) {
        int qcol = quarter * 96;
        float acc[2][6][4] = {};

        issue(0, 0, qcol); CP_COMMIT();
        issue(1, 1, qcol); CP_COMMIT();
        issue(2, 2, qcol); CP_COMMIT();

        for (int ch = 0; ch < 24; ++ch) {
            int st = ch & 3;
            CP_WAIT2();
            __syncthreads();
            if (ch + 3 < 24) issue(ch + 3, (ch + 3) & 3, qcol);
            CP_COMMIT();
            uint32_t sa = su + st * STG + aoff;
            uint32_t af[2][4];
            #pragma unroll
            for (int band = 0; band < 2; ++band) {
                int rb = wm * 32 + band * 16 + arow;
                ldmx4(af[band], sa + SWO(rb, au));
            }
            uint32_t sbB = su + st * STG + B_OFF + qk * 3328 + brow_off;
            #pragma unroll
            for (int np = 0; np < 3; ++np) {
                int cb = wn * 48 + np * 16;
                uint32_t bh[4];
                ldmx4t(bh, sbB + cb * 2);
                #pragma unroll
                for (int band = 0; band < 2; ++band)
                    #pragma unroll
                    for (int sub = 0; sub < 2; ++sub)
                        mma16816h(acc[band][2 * np + sub], af[band], bh + 2 * sub);
            }
        }

        // ---- epilogue: exchange K accs via smem, rowwise dot ---------------
        __syncthreads();
        float (*sEx)[97] = (float (*)[97])smd;
        if (qk == 1) {
            #pragma unroll
            for (int band = 0; band < 2; ++band)
                #pragma unroll
                for (int h = 0; h < 2; ++h) {
                    int row = wm * 32 + band * 16 + (lane >> 2) + 8 * h;
                    #pragma unroll
                    for (int nt = 0; nt < 6; ++nt) {
                        int c0 = wn * 48 + nt * 8 + (lane & 3) * 2;
                        sEx[row][c0] = acc[band][nt][2 * h];
                        sEx[row][c0 + 1] = acc[band][nt][2 * h + 1];
                    }
                }
        }
        __syncthreads();
        if (qk == 0) {
            #pragma unroll
            for (int band = 0; band < 2; ++band)
                #pragma unroll
                for (int h = 0; h < 2; ++h) {
                    int row = wm * 32 + band * 16 + (lane >> 2) + 8 * h;
                    float p = 0.f;
                    #pragma unroll
                    for (int nt = 0; nt < 6; ++nt) {
                        int c0 = wn * 48 + nt * 8 + (lane & 3) * 2;
                        p += acc[band][nt][2 * h] * sEx[row][c0]
                           + acc[band][nt][2 * h + 1] * sEx[row][c0 + 1];
                    }
                    p += __shfl_xor_sync(0xffffffffu, p, 1);
                    p += __shfl_xor_sync(0xffffffffu, p, 2);
                    if ((lane & 3) == 0) {
                        int g = m0 + row;
                        if (g < rows2) {
                            int bb = g >= M;
                            int mm = g - (bb ? M : 0);
                            int i = r + mm, j = mm;
                            int head = quarter * 2 + wn;
                            g_dots[((size_t)(bb * H + head) * L + i) * L + j] = p * SCALE;
                        }
                    }
                }
        }
        __syncthreads();
    }
}

// ---------------- softmax + attn @ v -----------------------------------------
__global__ __launch_bounds__(192) void softmax_av_kernel() {
    int i = blockIdx.x, h = blockIdx.y, b = blockIdx.z;
    int t = threadIdx.x;
    const float* drow = g_dots + ((size_t)(b * H + h) * L + i) * L;

    __shared__ float sP[192];
    __shared__ float swork[6];
    __shared__ float smax, ssum;
    __shared__ float sAcc[4][48];

    float val = (t <= i) ? drow[t] : -INFINITY;
    float m = val;
    #pragma unroll
    for (int off = 16; off; off >>= 1)
        m = fmaxf(m, __shfl_xor_sync(0xffffffffu, m, off));
    if ((t & 31) == 0) swork[t >> 5] = m;
    __syncthreads();
    if (t == 0) {
        float mm = swork[0];
        #pragma unroll
        for (int k = 1; k < 6; ++k) mm = fmaxf(mm, swork[k]);
        smax = mm;
    }
    __syncthreads();
    float p = (t <= i) ? expf(val - smax) : 0.f;
    sP[t] = p;
    float s = p;
    #pragma unroll
    for (int off = 16; off; off >>= 1)
        s += __shfl_xor_sync(0xffffffffu, s, off);
    if ((t & 31) == 0) swork[t >> 5] = s;
    __syncthreads();
    if (t == 0) {
        float acc = 0.f;
        #pragma unroll
        for (int k = 0; k < 6; ++k) acc += swork[k];
        ssum = acc;
    }
    __syncthreads();
    float inv = 1.0f / ssum;

    int d = t % 48, q = t / 48;
    float acc = 0.f;
    for (int j = q; j <= i; j += 4)
        acc += sP[j] * g_v[(size_t)(b * L + j) * D + h * DH + d];
    sAcc[q][d] = acc;
    __syncthreads();
    if (t < 48) {
        float o = (sAcc[0][t] + sAcc[1][t] + sAcc[2][t] + sAcc[3][t]) * inv;
        g_ctx[(size_t)(b * L + i) * D + h * DH + t] = o;
    }
}

extern "C" void kernel_launch(void* const* d_in, const int* in_sizes, int n_in,
                              void* d_out, int out_size) {
    const float* x     = (const float*)d_in[0];
    const float* gamma = (const float*)d_in[1];
    const float* beta  = (const float*)d_in[2];
    const float* uq    = (const float*)d_in[3];
    const float* uk    = (const float*)d_in[4];
    const float* wv    = (const float*)d_in[5];
    const float* wo    = (const float*)d_in[6];
    const float* bo    = (const float*)d_in[7];
    float* out = (float*)d_out;
    (void)in_sizes; (void)n_in; (void)out_size;

    cudaFuncSetAttribute(diag_mma_kernel,
                         cudaFuncAttributeMaxDynamicSharedMemorySize, SMEM_TOT);

    // 1) streaming fp32->fp16 convert of u (native layout, no transpose)
    conv_kernel<<<(L * D * D) / 1024, 256>>>(uq, uk);
    // 2) LayerNorm (+ fp16)
    ln_kernel<<<BATCH * L, 128>>>(x, gamma, beta);
    // 3) v = xn @ w_v
    vproj_kernel<<<dim3(6, 6), 256>>>(wv);
    // 4) per-diagonal dual GEMM + per-head dots (single-term fp16 mma)
    diag_mma_kernel<<<dim3(6, L), 256, SMEM_TOT>>>();
    // 5) causal softmax + attn @ v
    softmax_av_kernel<<<dim3(L, H, BATCH), 192>>>();
    // 6) out = ctx @ w_o + b_o
    oproj_kernel<<<dim3(6, 6), 256>>>(wo, bo, out);
}